// round 16
// baseline (speedup 1.0000x reference)
#include <cuda_runtime.h>
#include <cuda_fp16.h>
#include <cstdint>

// ============================================================================
// GptOssMoEExperts: router collapses to identity (softmax over top-k sums to 1
// and the expert MLP is shared), so
//   out = ((x@Wg^T+bg) * silu(x@Wu^T+bu)) @ W2^T + b2
// R16: GEMM1 re-tiled for wave efficiency: 40 out cols/CTA (B tile = 40 gate +
// 40 up rows), warp 32x80, grid 32x72=2304 -> 7.78 -> 8 waves (eff 0.973 vs
// 0.927). ~180 regs (under the ~200 wall R5/R14 hit). Register-paired SiLU
// (boundary at row 40 = multiple of 8 -> frag j pairs j+5). 4-stage cp.async,
// cross-kt fragment prefetch, interleaved LDGSTS quarters.
// GEMM2: R15 BN=160 (2 waves @0.973). cvt: merged single launch.
// ============================================================================

#define SEQ   4096
#define HID   2880
#define INTER 2880
#define NGU   (2 * INTER)   // 5760

static constexpr int BM   = 128;
static constexpr int BK   = 64;              // fp16 elems -> 128B rows
static constexpr int KIT  = HID / BK;        // 45

// GEMM1 (40 out cols: 80 B rows)
static constexpr int NC1     = 40;                    // out cols per CTA
static constexpr int BROWS1  = 2 * NC1;               // 80
static constexpr int STAGES1 = 4;
static constexpr int OFF_B1  = BM * 128;              // 16384
static constexpr int STAGE1  = OFF_B1 + BROWS1 * 128; // 26624
static constexpr int SMEM1   = STAGES1 * STAGE1;      // 106496

// GEMM2 (R15: BN=160)
static constexpr int BN2     = 160;
static constexpr int STAGES2 = 3;
static constexpr int OFF_B2  = BM * 128;              // 16384
static constexpr int STAGE2  = OFF_B2 + BN2 * 128;    // 36864
static constexpr int SMEM2   = STAGES2 * STAGE2;      // 110592

// ---------------------------------------------------------------------------
// Scratch (__device__ globals = sanctioned allocation-free scratch)
// ---------------------------------------------------------------------------
__device__ __align__(128) __half g_xh [(size_t)SEQ * HID];
__device__ __align__(128) __half g_w1h[(size_t)NGU * HID];
__device__ __align__(128) __half g_w2h[(size_t)HID * INTER];
__device__ __align__(128) __half g_hh [(size_t)SEQ * INTER];

// ---------------------------------------------------------------------------
// PTX helpers
// ---------------------------------------------------------------------------
__device__ __forceinline__ uint32_t smem_u32(const void* p) {
    uint32_t a;
    asm("{ .reg .u64 t; cvta.to.shared.u64 t, %1; cvt.u32.u64 %0, t; }" : "=r"(a) : "l"(p));
    return a;
}
__device__ __forceinline__ void ldsm4(uint32_t* r, uint32_t a) {
    asm volatile("ldmatrix.sync.aligned.m8n8.x4.shared.b16 {%0,%1,%2,%3}, [%4];"
                 : "=r"(r[0]), "=r"(r[1]), "=r"(r[2]), "=r"(r[3]) : "r"(a));
}
__device__ __forceinline__ void mma16816(float* d, const uint32_t* a, const uint32_t* b) {
    asm volatile(
        "mma.sync.aligned.m16n8k16.row.col.f32.f16.f16.f32 "
        "{%0,%1,%2,%3}, {%4,%5,%6,%7}, {%8,%9}, {%0,%1,%2,%3};"
        : "+f"(d[0]), "+f"(d[1]), "+f"(d[2]), "+f"(d[3])
        : "r"(a[0]), "r"(a[1]), "r"(a[2]), "r"(a[3]), "r"(b[0]), "r"(b[1]));
}
__device__ __forceinline__ void cp16(uint32_t s, const void* g) {
    asm volatile("cp.async.cg.shared.global [%0], [%1], 16;" :: "r"(s), "l"(g) : "memory");
}
#define CP_COMMIT()  asm volatile("cp.async.commit_group;" ::: "memory")
#define CP_WAIT_1()  asm volatile("cp.async.wait_group 1;"  ::: "memory")

// ---------------------------------------------------------------------------
// Merged fp32 -> fp16 conversion for all three inputs (one launch)
// ---------------------------------------------------------------------------
__global__ void cvt3_kernel(const float4* __restrict__ s0, uint2* __restrict__ d0, int n0,
                            const float4* __restrict__ s1, uint2* __restrict__ d1, int n1,
                            const float4* __restrict__ s2, uint2* __restrict__ d2, int n2) {
    int i = blockIdx.x * blockDim.x + threadIdx.x;
    const float4* s;  uint2* d;  int j;
    if (i < n0)            { s = s0; d = d0; j = i; }
    else if (i < n0 + n1)  { s = s1; d = d1; j = i - n0; }
    else if (i < n0 + n1 + n2) { s = s2; d = d2; j = i - n0 - n1; }
    else return;
    float4 v = s[j];
    __half2 a = __floats2half2_rn(v.x, v.y);
    __half2 b = __floats2half2_rn(v.z, v.w);
    uint2 o;
    o.x = *reinterpret_cast<uint32_t*>(&a);
    o.y = *reinterpret_cast<uint32_t*>(&b);
    d[j] = o;
}

// ---------------------------------------------------------------------------
// GEMM1 (register-paired SiLU): h[:, nBase:nBase+40] =
//   (x@Wg^T+bg) * silu(x@Wu^T+bu)
// B tile rows 0-39 = W1 gate rows nBase.., rows 40-79 = W1 up rows
// INTER+nBase.. (same out cols). 4 M-warps, warp tile 32x80: n8 frag j (0-4)
// gate pairs frag j+5 up in-thread (boundary 40 = multiple of 8).
// ---------------------------------------------------------------------------
__global__ void __launch_bounds__(128, 2)
gemm1_fused(const __half* __restrict__ A, const __half* __restrict__ W1,
            const float* __restrict__ b1, __half* __restrict__ h) {
    extern __shared__ __align__(128) char smem[];
    const uint32_t sb0 = smem_u32(smem);
    const int tid = threadIdx.x;
    const int l   = tid & 31;
    const int wm  = tid >> 5;          // 0..3 (all M-warps)
    const int mBase = blockIdx.x * BM;
    const int nBase = blockIdx.y * NC1;

    const int rowT = tid >> 3;                    // 0..15
    const int u8   = tid & 7;
    const uint32_t aSmem = (uint32_t)rowT * 128 + (uint32_t)((u8 ^ (rowT & 7)) << 4);
    const uint32_t bSmem = OFF_B1 + aSmem;
    const __half* gAn = A  + (size_t)(mBase + rowT) * HID + u8 * 8;
    const __half* gBg = W1 + (size_t)(nBase + rowT) * HID + u8 * 8;          // gate row rowT
    const __half* gBu = W1 + (size_t)(INTER + nBase + rowT) * HID + u8 * 8;  // up row rowT

    // B chunk k covers tile rows rowT+16k (k=0..4; 80 rows).
    //   k=0,1: gate rows.  k=2: rows 32-47 — rowT<8 gate row 32+rowT,
    //   rowT>=8 up row rowT-8.  k=3,4: up rows (16k-40 offset).
    auto bptr = [&](int k) -> const __half* {
        if (k < 2)  return gBg + (size_t)k * 16 * HID;
        if (k == 2) return (rowT < 8) ? gBg + (size_t)32 * HID
                                      : gBu - (size_t)8 * HID;
        return gBu + (size_t)(16 * k - 40) * HID;
    };
    // Quarters: p0 A{0,1}+B{0,1}; p1 A{2,3}+B{2}; p2 A{4,5}+B{3}; p3 A{6,7}+B{4}.
    auto load_part = [&](uint32_t sbSlot, int part) {
        #pragma unroll
        for (int k = 2 * part; k < 2 * part + 2; k++)
            cp16(sbSlot + aSmem + k * 2048, gAn + (size_t)k * 16 * HID);
        if (part == 0) {
            cp16(sbSlot + bSmem,        bptr(0));
            cp16(sbSlot + bSmem + 2048, bptr(1));
        } else {
            const int k = part + 1;                 // 2, 3, 4
            cp16(sbSlot + bSmem + k * 2048, bptr(k));
        }
    };

    const int l7  = l & 7;
    const int lhi = l >> 4;
    const int le  = l & 15;
    const int q   = l >> 3;
    const int aRow0 = wm * 32 + le;
    const int bRowO = ((q >> 1) << 3) + l7;
    const int bUnit = q & 1;

    auto loadA = [&](uint32_t af[2][4], uint32_t sA, int ks) {
        #pragma unroll
        for (int i = 0; i < 2; i++)
            ldsm4(af[i], sA + (uint32_t)(aRow0 + i * 16) * 128 +
                           (uint32_t)(((ks * 2 + lhi) ^ l7) << 4));
    };
    auto loadB = [&](uint32_t bf[5][4], uint32_t sB, int ks) {
        #pragma unroll
        for (int p = 0; p < 5; p++)
            ldsm4(bf[p], sB + (uint32_t)(bRowO + p * 16) * 128 +
                           (uint32_t)(((ks * 2 + bUnit) ^ l7) << 4));
    };

    float acc[2][10][4] = {};     // j 0-4 gate (40 cols), j 5-9 up (paired)
    uint32_t af[2][2][4], bf[2][5][4];

    #pragma unroll
    for (int s = 0; s < STAGES1 - 1; s++) {               // prologue: 3 stages
        const uint32_t sbSlot = sb0 + s * STAGE1;
        #pragma unroll
        for (int p = 0; p < 4; p++) load_part(sbSlot, p);
        CP_COMMIT();
        gAn += BK;  gBg += BK;  gBu += BK;
    }

    CP_WAIT_1();
    __syncthreads();
    loadA(af[0], sb0, 0);
    loadB(bf[0], sb0 + OFF_B1, 0);

    for (int kt = 0; kt < KIT; kt++) {
        const int  nk     = kt + STAGES1 - 1;
        const bool doLoad = nk < KIT;
        const uint32_t sbSlot = sb0 + (nk % STAGES1) * STAGE1;

        const uint32_t sA  = sb0 + (kt % STAGES1) * STAGE1;
        const uint32_t sB  = sA + OFF_B1;
        const uint32_t sAn = sb0 + ((kt + 1) % STAGES1) * STAGE1;
        const uint32_t sBn = sAn + OFF_B1;

        #pragma unroll
        for (int ks = 0; ks < 4; ks++) {
            const int cur = ks & 1, nxt = cur ^ 1;
            if (ks < 3) {
                loadA(af[nxt], sA, ks + 1);
                loadB(bf[nxt], sB, ks + 1);
            } else if (kt + 1 < KIT) {
                loadA(af[nxt], sAn, 0);       // cross-kt prefetch
                loadB(bf[nxt], sBn, 0);
            }
            if (doLoad) load_part(sbSlot, ks);
            #pragma unroll
            for (int i = 0; i < 2; i++)
                #pragma unroll
                for (int p = 0; p < 5; p++) {
                    mma16816(acc[i][2 * p],     af[cur][i], &bf[cur][p][0]);
                    mma16816(acc[i][2 * p + 1], af[cur][i], &bf[cur][p][2]);
                }
        }
        CP_COMMIT();
        gAn += BK;  gBg += BK;  gBu += BK;
        if (kt + 1 < KIT) {
            CP_WAIT_1();
            __syncthreads();
        }
    }

    // ---- epilogue: register-paired SiLU, h fp16 ----
    const int r00 = mBase + wm * 32 + (l >> 2);
    const int cL  = 2 * (l & 3);

    #pragma unroll
    for (int j = 0; j < 5; j++) {                 // gate j pairs up j+5
        const int c = cL + j * 8;
        const float bg0 = __ldg(b1 + nBase + c);
        const float bg1 = __ldg(b1 + nBase + c + 1);
        const float bu0 = __ldg(b1 + INTER + nBase + c);
        const float bu1 = __ldg(b1 + INTER + nBase + c + 1);
        #pragma unroll
        for (int i = 0; i < 2; i++)
            #pragma unroll
            for (int hh = 0; hh < 2; hh++) {
                const int r = r00 + i * 16 + hh * 8;
                const float g0 = acc[i][j][2 * hh]         + bg0;
                const float g1 = acc[i][j][2 * hh + 1]     + bg1;
                const float u0 = acc[i][j + 5][2 * hh]     + bu0;
                const float u1 = acc[i][j + 5][2 * hh + 1] + bu1;
                const float h0 = g0 * u0 * (1.0f / (1.0f + __expf(-u0)));
                const float h1 = g1 * u1 * (1.0f / (1.0f + __expf(-u1)));
                *reinterpret_cast<__half2*>(
                    h + (size_t)r * INTER + nBase + c) =
                    __floats2half2_rn(h0, h1);
            }
    }
}

// ---------------------------------------------------------------------------
// GEMM2: out = h @ W2^T + b2 (fp32). CTA 128x160, 4 warps (2Mx2N),
// warp tile 64x80. 3-stage cp.async, interleaved LDGSTS quarters.
// Grid 576 -> 2 waves @ 0.973. (R15 proven, unchanged)
// ---------------------------------------------------------------------------
__global__ void __launch_bounds__(128, 2)
gemm2(const __half* __restrict__ A, const __half* __restrict__ B,
      const float* __restrict__ bias, float* __restrict__ oF) {
    extern __shared__ __align__(128) char smem[];
    const uint32_t sb0 = smem_u32(smem);
    const int tid = threadIdx.x;
    const int l   = tid & 31;
    const int wid = tid >> 5;
    const int wm  = wid >> 1;
    const int wn  = wid & 1;
    const int mBase = blockIdx.x * BM;
    const int nBase = blockIdx.y * BN2;

    const int rowT = tid >> 3;
    const int u8   = tid & 7;
    const uint32_t aSmem = (uint32_t)rowT * 128 + (uint32_t)((u8 ^ (rowT & 7)) << 4);
    const uint32_t bSmem = OFF_B2 + aSmem;
    const __half* gAn = A + (size_t)(mBase + rowT) * HID + u8 * 8;
    const __half* gBn = B + (size_t)(nBase + rowT) * HID + u8 * 8;

    auto load_part = [&](uint32_t sbSlot, int part) {
        #pragma unroll
        for (int k = 2 * part; k < 2 * part + 2; k++)
            cp16(sbSlot + aSmem + k * 2048, gAn + (size_t)k * 16 * HID);
        const int b0 = (part < 2) ? 3 * part : (6 + 2 * (part - 2));
        const int nb = (part < 2) ? 3 : 2;
        #pragma unroll
        for (int k = b0; k < b0 + nb; k++)
            cp16(sbSlot + bSmem + k * 2048, gBn + (size_t)k * 16 * HID);
    };

    const int l7  = l & 7;
    const int lhi = l >> 4;
    const int le  = l & 15;
    const int q   = l >> 3;
    const int aRow0 = wm * 64 + le;
    const int bRowO = wn * 80 + ((q >> 1) << 3) + l7;
    const int bUnit = q & 1;

    auto loadA = [&](uint32_t af[4][4], uint32_t sA, int ks) {
        #pragma unroll
        for (int i = 0; i < 4; i++)
            ldsm4(af[i], sA + (uint32_t)(aRow0 + i * 16) * 128 +
                           (uint32_t)(((ks * 2 + lhi) ^ l7) << 4));
    };
    auto loadB = [&](uint32_t bf[5][4], uint32_t sB, int ks) {
        #pragma unroll
        for (int p = 0; p < 5; p++)
            ldsm4(bf[p], sB + (uint32_t)(bRowO + p * 16) * 128 +
                           (uint32_t)(((ks * 2 + bUnit) ^ l7) << 4));
    };

    float acc[4][10][4] = {};
    uint32_t af[2][4][4], bf[2][5][4];

    #pragma unroll
    for (int s = 0; s < STAGES2 - 1; s++) {
        const uint32_t sbSlot = sb0 + s * STAGE2;
        #pragma unroll
        for (int p = 0; p < 4; p++) load_part(sbSlot, p);
        CP_COMMIT();
        gAn += BK;  gBn += BK;
    }

    for (int kt = 0; kt < KIT; kt++) {
        CP_WAIT_1();
        __syncthreads();

        const int  nk     = kt + STAGES2 - 1;
        const bool doLoad = nk < KIT;
        const uint32_t sbSlot = sb0 + (nk % STAGES2) * STAGE2;

        const uint32_t sA = sb0 + (kt % STAGES2) * STAGE2;
        const uint32_t sB = sA + OFF_B2;

        loadA(af[0], sA, 0);
        loadB(bf[0], sB, 0);
        #pragma unroll
        for (int ks = 0; ks < 4; ks++) {
            const int cur = ks & 1, nxt = cur ^ 1;
            if (ks < 3) {
                loadA(af[nxt], sA, ks + 1);
                loadB(bf[nxt], sB, ks + 1);
            }
            if (doLoad) load_part(sbSlot, ks);
            #pragma unroll
            for (int i = 0; i < 4; i++)
                #pragma unroll
                for (int p = 0; p < 5; p++) {
                    mma16816(acc[i][2 * p],     af[cur][i], &bf[cur][p][0]);
                    mma16816(acc[i][2 * p + 1], af[cur][i], &bf[cur][p][2]);
                }
        }
        CP_COMMIT();
        gAn += BK;  gBn += BK;
    }

    const int r00 = mBase + wm * 64 + (l >> 2);
    const int cB  = nBase + wn * 80 + 2 * (l & 3);

    #pragma unroll
    for (int i = 0; i < 4; i++)
        #pragma unroll
        for (int j = 0; j < 10; j++) {
            const int c = cB + j * 8;
            const float b0 = __ldg(bias + c), b1v = __ldg(bias + c + 1);
            #pragma unroll
            for (int hh = 0; hh < 2; hh++) {
                const int r = r00 + i * 16 + hh * 8;
                *reinterpret_cast<float2*>(oF + (size_t)r * HID + c) =
                    make_float2(acc[i][j][2 * hh] + b0,
                                acc[i][j][2 * hh + 1] + b1v);
            }
        }
}

// ---------------------------------------------------------------------------
// Host
// ---------------------------------------------------------------------------
extern "C" void kernel_launch(void* const* d_in, const int* in_sizes, int n_in,
                              void* d_out, int out_size) {
    const float* x  = (const float*)d_in[0];   // hidden_states (4096, 2880)
    const float* w1 = (const float*)d_in[3];   // gate_up_w (5760, 2880)
    const float* b1 = (const float*)d_in[4];   // gate_up_b (5760,)
    const float* w2 = (const float*)d_in[5];   // down_w (2880, 2880)
    const float* b2 = (const float*)d_in[6];   // down_b (2880,)
    float* out = (float*)d_out;                // (4096, 2880) fp32

    void *px, *pw1, *pw2, *ph;
    cudaGetSymbolAddress(&px,  g_xh);
    cudaGetSymbolAddress(&pw1, g_w1h);
    cudaGetSymbolAddress(&pw2, g_w2h);
    cudaGetSymbolAddress(&ph,  g_hh);

    // fp32 -> fp16: single merged launch
    {
        const int n0 = (SEQ * HID) / 4;
        const int n1 = (NGU * HID) / 4;
        const int n2 = (HID * INTER) / 4;
        const int nt = n0 + n1 + n2;
        cvt3_kernel<<<(nt + 255) / 256, 256>>>(
            (const float4*)x,  (uint2*)px,  n0,
            (const float4*)w1, (uint2*)pw1, n1,
            (const float4*)w2, (uint2*)pw2, n2);
    }

    cudaFuncSetAttribute(gemm1_fused,
                         cudaFuncAttributeMaxDynamicSharedMemorySize, SMEM1);
    cudaFuncSetAttribute(gemm2,
                         cudaFuncAttributeMaxDynamicSharedMemorySize, SMEM2);

    // GEMM1 fused: h = (x@Wg^T+bg) * silu(x@Wu^T+bu)   (fp16, 4096 x 2880)
    gemm1_fused<<<dim3(SEQ / BM, INTER / NC1), 128, SMEM1>>>(
        (const __half*)px, (const __half*)pw1, b1, (__half*)ph);

    // GEMM2: out = h @ W2^T + b2   (fp32, 4096 x 2880)
    gemm2<<<dim3(SEQ / BM, HID / BN2), 128, SMEM2>>>(
        (const __half*)ph, (const __half*)pw2, b2, out);
}

// round 17
// speedup vs baseline: 1.0225x; 1.0225x over previous
#include <cuda_runtime.h>
#include <cuda_fp16.h>
#include <cstdint>

// ============================================================================
// GptOssMoEExperts: router collapses to identity (softmax over top-k sums to 1
// and the expert MLP is shared), so
//   out = ((x@Wg^T+bg) * silu(x@Wu^T+bu)) @ W2^T + b2
// R17 = R15 (best: 469.8us) with cvt3 given MLP=2 (2 independent float4 per
// thread). GEMM1: R12 32x96-paired SiLU fusion, 4-stage, cross-kt prefetch.
// GEMM2: BN=160 (grid 576 -> 2 waves @0.973), warp 64x80, 3-stage.
// R16's 40-col GEMM1 regressed (A re-streamed 72x vs 60x) — reverted.
// ============================================================================

#define SEQ   4096
#define HID   2880
#define INTER 2880
#define NGU   (2 * INTER)   // 5760

static constexpr int BM   = 128;
static constexpr int BK   = 64;              // fp16 elems -> 128B rows
static constexpr int KIT  = HID / BK;        // 45

// GEMM1 (R12)
static constexpr int BN1     = 96;                    // 48 gate + 48 up rows
static constexpr int STAGES1 = 4;
static constexpr int OFF_B1  = BM * 128;              // 16384
static constexpr int STAGE1  = OFF_B1 + BN1 * 128;    // 28672
static constexpr int SMEM1   = STAGES1 * STAGE1;      // 114688

// GEMM2 (R15: BN=160)
static constexpr int BN2     = 160;
static constexpr int STAGES2 = 3;
static constexpr int OFF_B2  = BM * 128;              // 16384
static constexpr int STAGE2  = OFF_B2 + BN2 * 128;    // 36864
static constexpr int SMEM2   = STAGES2 * STAGE2;      // 110592

// ---------------------------------------------------------------------------
// Scratch (__device__ globals = sanctioned allocation-free scratch)
// ---------------------------------------------------------------------------
__device__ __align__(128) __half g_xh [(size_t)SEQ * HID];
__device__ __align__(128) __half g_w1h[(size_t)NGU * HID];
__device__ __align__(128) __half g_w2h[(size_t)HID * INTER];
__device__ __align__(128) __half g_hh [(size_t)SEQ * INTER];

// ---------------------------------------------------------------------------
// PTX helpers
// ---------------------------------------------------------------------------
__device__ __forceinline__ uint32_t smem_u32(const void* p) {
    uint32_t a;
    asm("{ .reg .u64 t; cvta.to.shared.u64 t, %1; cvt.u32.u64 %0, t; }" : "=r"(a) : "l"(p));
    return a;
}
__device__ __forceinline__ void ldsm4(uint32_t* r, uint32_t a) {
    asm volatile("ldmatrix.sync.aligned.m8n8.x4.shared.b16 {%0,%1,%2,%3}, [%4];"
                 : "=r"(r[0]), "=r"(r[1]), "=r"(r[2]), "=r"(r[3]) : "r"(a));
}
__device__ __forceinline__ void mma16816(float* d, const uint32_t* a, const uint32_t* b) {
    asm volatile(
        "mma.sync.aligned.m16n8k16.row.col.f32.f16.f16.f32 "
        "{%0,%1,%2,%3}, {%4,%5,%6,%7}, {%8,%9}, {%0,%1,%2,%3};"
        : "+f"(d[0]), "+f"(d[1]), "+f"(d[2]), "+f"(d[3])
        : "r"(a[0]), "r"(a[1]), "r"(a[2]), "r"(a[3]), "r"(b[0]), "r"(b[1]));
}
__device__ __forceinline__ void cp16(uint32_t s, const void* g) {
    asm volatile("cp.async.cg.shared.global [%0], [%1], 16;" :: "r"(s), "l"(g) : "memory");
}
#define CP_COMMIT()  asm volatile("cp.async.commit_group;" ::: "memory")
#define CP_WAIT_1()  asm volatile("cp.async.wait_group 1;"  ::: "memory")

// ---------------------------------------------------------------------------
// Merged fp32 -> fp16 conversion, 2 independent float4 chunks per thread.
// Chunks for one thread are gridSize apart (coalesced within warps).
// ---------------------------------------------------------------------------
__global__ void cvt3_kernel(const float4* __restrict__ s0, uint2* __restrict__ d0, int n0,
                            const float4* __restrict__ s1, uint2* __restrict__ d1, int n1,
                            const float4* __restrict__ s2, uint2* __restrict__ d2, int n2) {
    const int nt   = n0 + n1 + n2;
    const int span = gridDim.x * blockDim.x;
    int i = blockIdx.x * blockDim.x + threadIdx.x;

    #pragma unroll
    for (int it = 0; it < 2; it++, i += span) {
        if (i >= nt) return;
        const float4* s;  uint2* d;  int j;
        if (i < n0)           { s = s0; d = d0; j = i; }
        else if (i < n0 + n1) { s = s1; d = d1; j = i - n0; }
        else                  { s = s2; d = d2; j = i - n0 - n1; }
        float4 v = s[j];
        __half2 a = __floats2half2_rn(v.x, v.y);
        __half2 b = __floats2half2_rn(v.z, v.w);
        uint2 o;
        o.x = *reinterpret_cast<uint32_t*>(&a);
        o.y = *reinterpret_cast<uint32_t*>(&b);
        d[j] = o;
    }
}

// ---------------------------------------------------------------------------
// GEMM1 (R12, register-paired SiLU fusion): CTA computes 48 output cols.
// B tile rows 0-47 = W1 gate rows, rows 48-95 = W1 up rows (same cols).
// 4 M-warps, warp tile 32x96: acc[i][j] gate pairs acc[i][j+6] up in-thread.
// 4-stage cp.async, cross-kt fragment prefetch, interleaved LDGSTS quarters.
// ---------------------------------------------------------------------------
__global__ void __launch_bounds__(128, 2)
gemm1_fused(const __half* __restrict__ A, const __half* __restrict__ W1,
            const float* __restrict__ b1, __half* __restrict__ h) {
    extern __shared__ __align__(128) char smem[];
    const uint32_t sb0 = smem_u32(smem);
    const int tid = threadIdx.x;
    const int l   = tid & 31;
    const int wm  = tid >> 5;          // 0..3 (all M-warps)
    const int mBase = blockIdx.x * BM;
    const int nBase = blockIdx.y * 48;

    const int rowT = tid >> 3;
    const int u8   = tid & 7;
    const uint32_t aSmem = (uint32_t)rowT * 128 + (uint32_t)((u8 ^ (rowT & 7)) << 4);
    const uint32_t bSmem = OFF_B1 + aSmem;
    const __half* gAn = A  + (size_t)(mBase + rowT) * HID + u8 * 8;
    const __half* gBg = W1 + (size_t)(nBase + rowT) * HID + u8 * 8;
    const __half* gBu = W1 + (size_t)(INTER + nBase + rowT) * HID + u8 * 8;

    auto bptr = [&](int k) -> const __half* {
        return (k < 3) ? gBg + (size_t)k * 16 * HID
                       : gBu + (size_t)(k - 3) * 16 * HID;
    };
    auto load_part = [&](uint32_t sbSlot, int part) {
        #pragma unroll
        for (int k = 2 * part; k < 2 * part + 2; k++)
            cp16(sbSlot + aSmem + k * 2048, gAn + (size_t)k * 16 * HID);
        if (part < 2) {
            #pragma unroll
            for (int k = 2 * part; k < 2 * part + 2; k++)
                cp16(sbSlot + bSmem + k * 2048, bptr(k));
        } else {
            const int k = part + 2;
            cp16(sbSlot + bSmem + k * 2048, bptr(k));
        }
    };

    const int l7  = l & 7;
    const int lhi = l >> 4;
    const int le  = l & 15;
    const int q   = l >> 3;
    const int aRow0 = wm * 32 + le;
    const int bRowO = ((q >> 1) << 3) + l7;
    const int bUnit = q & 1;

    auto loadA = [&](uint32_t af[2][4], uint32_t sA, int ks) {
        #pragma unroll
        for (int i = 0; i < 2; i++)
            ldsm4(af[i], sA + (uint32_t)(aRow0 + i * 16) * 128 +
                           (uint32_t)(((ks * 2 + lhi) ^ l7) << 4));
    };
    auto loadB = [&](uint32_t bf[6][4], uint32_t sB, int ks) {
        #pragma unroll
        for (int p = 0; p < 6; p++)
            ldsm4(bf[p], sB + (uint32_t)(bRowO + p * 16) * 128 +
                           (uint32_t)(((ks * 2 + bUnit) ^ l7) << 4));
    };

    float acc[2][12][4] = {};
    uint32_t af[2][2][4], bf[2][6][4];

    #pragma unroll
    for (int s = 0; s < STAGES1 - 1; s++) {
        const uint32_t sbSlot = sb0 + s * STAGE1;
        #pragma unroll
        for (int p = 0; p < 4; p++) load_part(sbSlot, p);
        CP_COMMIT();
        gAn += BK;  gBg += BK;  gBu += BK;
    }

    CP_WAIT_1();
    __syncthreads();
    loadA(af[0], sb0, 0);
    loadB(bf[0], sb0 + OFF_B1, 0);

    for (int kt = 0; kt < KIT; kt++) {
        const int  nk     = kt + STAGES1 - 1;
        const bool doLoad = nk < KIT;
        const uint32_t sbSlot = sb0 + (nk % STAGES1) * STAGE1;

        const uint32_t sA  = sb0 + (kt % STAGES1) * STAGE1;
        const uint32_t sB  = sA + OFF_B1;
        const uint32_t sAn = sb0 + ((kt + 1) % STAGES1) * STAGE1;
        const uint32_t sBn = sAn + OFF_B1;

        #pragma unroll
        for (int ks = 0; ks < 4; ks++) {
            const int cur = ks & 1, nxt = cur ^ 1;
            if (ks < 3) {
                loadA(af[nxt], sA, ks + 1);
                loadB(bf[nxt], sB, ks + 1);
            } else if (kt + 1 < KIT) {
                loadA(af[nxt], sAn, 0);       // cross-kt prefetch
                loadB(bf[nxt], sBn, 0);
            }
            if (doLoad) load_part(sbSlot, ks);
            #pragma unroll
            for (int i = 0; i < 2; i++)
                #pragma unroll
                for (int p = 0; p < 6; p++) {
                    mma16816(acc[i][2 * p],     af[cur][i], &bf[cur][p][0]);
                    mma16816(acc[i][2 * p + 1], af[cur][i], &bf[cur][p][2]);
                }
        }
        CP_COMMIT();
        gAn += BK;  gBg += BK;  gBu += BK;
        if (kt + 1 < KIT) {
            CP_WAIT_1();
            __syncthreads();
        }
    }

    // ---- epilogue: register-paired SiLU, h fp16 ----
    const int r00 = mBase + wm * 32 + (l >> 2);
    const int cL  = 2 * (l & 3);

    #pragma unroll
    for (int j = 0; j < 6; j++) {                 // gate j pairs up j+6
        const int c = cL + j * 8;
        const float bg0 = __ldg(b1 + nBase + c);
        const float bg1 = __ldg(b1 + nBase + c + 1);
        const float bu0 = __ldg(b1 + INTER + nBase + c);
        const float bu1 = __ldg(b1 + INTER + nBase + c + 1);
        #pragma unroll
        for (int i = 0; i < 2; i++)
            #pragma unroll
            for (int hh = 0; hh < 2; hh++) {
                const int r = r00 + i * 16 + hh * 8;
                const float g0 = acc[i][j][2 * hh]         + bg0;
                const float g1 = acc[i][j][2 * hh + 1]     + bg1;
                const float u0 = acc[i][j + 6][2 * hh]     + bu0;
                const float u1 = acc[i][j + 6][2 * hh + 1] + bu1;
                const float h0 = g0 * u0 * (1.0f / (1.0f + __expf(-u0)));
                const float h1 = g1 * u1 * (1.0f / (1.0f + __expf(-u1)));
                *reinterpret_cast<__half2*>(
                    h + (size_t)r * INTER + nBase + c) =
                    __floats2half2_rn(h0, h1);
            }
    }
}

// ---------------------------------------------------------------------------
// GEMM2: out = h @ W2^T + b2 (fp32). CTA 128x160, 4 warps (2Mx2N),
// warp tile 64x80. 3-stage cp.async, interleaved LDGSTS quarters.
// Grid 576 -> 2 waves @ 0.973. (R15 proven, unchanged)
// ---------------------------------------------------------------------------
__global__ void __launch_bounds__(128, 2)
gemm2(const __half* __restrict__ A, const __half* __restrict__ B,
      const float* __restrict__ bias, float* __restrict__ oF) {
    extern __shared__ __align__(128) char smem[];
    const uint32_t sb0 = smem_u32(smem);
    const int tid = threadIdx.x;
    const int l   = tid & 31;
    const int wid = tid >> 5;
    const int wm  = wid >> 1;
    const int wn  = wid & 1;
    const int mBase = blockIdx.x * BM;
    const int nBase = blockIdx.y * BN2;

    const int rowT = tid >> 3;
    const int u8   = tid & 7;
    const uint32_t aSmem = (uint32_t)rowT * 128 + (uint32_t)((u8 ^ (rowT & 7)) << 4);
    const uint32_t bSmem = OFF_B2 + aSmem;
    const __half* gAn = A + (size_t)(mBase + rowT) * HID + u8 * 8;
    const __half* gBn = B + (size_t)(nBase + rowT) * HID + u8 * 8;

    auto load_part = [&](uint32_t sbSlot, int part) {
        #pragma unroll
        for (int k = 2 * part; k < 2 * part + 2; k++)
            cp16(sbSlot + aSmem + k * 2048, gAn + (size_t)k * 16 * HID);
        const int b0 = (part < 2) ? 3 * part : (6 + 2 * (part - 2));
        const int nb = (part < 2) ? 3 : 2;
        #pragma unroll
        for (int k = b0; k < b0 + nb; k++)
            cp16(sbSlot + bSmem + k * 2048, gBn + (size_t)k * 16 * HID);
    };

    const int l7  = l & 7;
    const int lhi = l >> 4;
    const int le  = l & 15;
    const int q   = l >> 3;
    const int aRow0 = wm * 64 + le;
    const int bRowO = wn * 80 + ((q >> 1) << 3) + l7;
    const int bUnit = q & 1;

    auto loadA = [&](uint32_t af[4][4], uint32_t sA, int ks) {
        #pragma unroll
        for (int i = 0; i < 4; i++)
            ldsm4(af[i], sA + (uint32_t)(aRow0 + i * 16) * 128 +
                           (uint32_t)(((ks * 2 + lhi) ^ l7) << 4));
    };
    auto loadB = [&](uint32_t bf[5][4], uint32_t sB, int ks) {
        #pragma unroll
        for (int p = 0; p < 5; p++)
            ldsm4(bf[p], sB + (uint32_t)(bRowO + p * 16) * 128 +
                           (uint32_t)(((ks * 2 + bUnit) ^ l7) << 4));
    };

    float acc[4][10][4] = {};
    uint32_t af[2][4][4], bf[2][5][4];

    #pragma unroll
    for (int s = 0; s < STAGES2 - 1; s++) {
        const uint32_t sbSlot = sb0 + s * STAGE2;
        #pragma unroll
        for (int p = 0; p < 4; p++) load_part(sbSlot, p);
        CP_COMMIT();
        gAn += BK;  gBn += BK;
    }

    for (int kt = 0; kt < KIT; kt++) {
        CP_WAIT_1();
        __syncthreads();

        const int  nk     = kt + STAGES2 - 1;
        const bool doLoad = nk < KIT;
        const uint32_t sbSlot = sb0 + (nk % STAGES2) * STAGE2;

        const uint32_t sA = sb0 + (kt % STAGES2) * STAGE2;
        const uint32_t sB = sA + OFF_B2;

        loadA(af[0], sA, 0);
        loadB(bf[0], sB, 0);
        #pragma unroll
        for (int ks = 0; ks < 4; ks++) {
            const int cur = ks & 1, nxt = cur ^ 1;
            if (ks < 3) {
                loadA(af[nxt], sA, ks + 1);
                loadB(bf[nxt], sB, ks + 1);
            }
            if (doLoad) load_part(sbSlot, ks);
            #pragma unroll
            for (int i = 0; i < 4; i++)
                #pragma unroll
                for (int p = 0; p < 5; p++) {
                    mma16816(acc[i][2 * p],     af[cur][i], &bf[cur][p][0]);
                    mma16816(acc[i][2 * p + 1], af[cur][i], &bf[cur][p][2]);
                }
        }
        CP_COMMIT();
        gAn += BK;  gBn += BK;
    }

    const int r00 = mBase + wm * 64 + (l >> 2);
    const int cB  = nBase + wn * 80 + 2 * (l & 3);

    #pragma unroll
    for (int i = 0; i < 4; i++)
        #pragma unroll
        for (int j = 0; j < 10; j++) {
            const int c = cB + j * 8;
            const float b0 = __ldg(bias + c), b1v = __ldg(bias + c + 1);
            #pragma unroll
            for (int hh = 0; hh < 2; hh++) {
                const int r = r00 + i * 16 + hh * 8;
                *reinterpret_cast<float2*>(oF + (size_t)r * HID + c) =
                    make_float2(acc[i][j][2 * hh] + b0,
                                acc[i][j][2 * hh + 1] + b1v);
            }
        }
}

// ---------------------------------------------------------------------------
// Host
// ---------------------------------------------------------------------------
extern "C" void kernel_launch(void* const* d_in, const int* in_sizes, int n_in,
                              void* d_out, int out_size) {
    const float* x  = (const float*)d_in[0];   // hidden_states (4096, 2880)
    const float* w1 = (const float*)d_in[3];   // gate_up_w (5760, 2880)
    const float* b1 = (const float*)d_in[4];   // gate_up_b (5760,)
    const float* w2 = (const float*)d_in[5];   // down_w (2880, 2880)
    const float* b2 = (const float*)d_in[6];   // down_b (2880,)
    float* out = (float*)d_out;                // (4096, 2880) fp32

    void *px, *pw1, *pw2, *ph;
    cudaGetSymbolAddress(&px,  g_xh);
    cudaGetSymbolAddress(&pw1, g_w1h);
    cudaGetSymbolAddress(&pw2, g_w2h);
    cudaGetSymbolAddress(&ph,  g_hh);

    // fp32 -> fp16: single launch, 2 chunks/thread
    {
        const int n0 = (SEQ * HID) / 4;
        const int n1 = (NGU * HID) / 4;
        const int n2 = (HID * INTER) / 4;
        const int nt = n0 + n1 + n2;
        const int nthreads = (nt + 1) / 2;
        cvt3_kernel<<<(nthreads + 255) / 256, 256>>>(
            (const float4*)x,  (uint2*)px,  n0,
            (const float4*)w1, (uint2*)pw1, n1,
            (const float4*)w2, (uint2*)pw2, n2);
    }

    cudaFuncSetAttribute(gemm1_fused,
                         cudaFuncAttributeMaxDynamicSharedMemorySize, SMEM1);
    cudaFuncSetAttribute(gemm2,
                         cudaFuncAttributeMaxDynamicSharedMemorySize, SMEM2);

    // GEMM1 fused: h = (x@Wg^T+bg) * silu(x@Wu^T+bu)   (fp16, 4096 x 2880)
    gemm1_fused<<<dim3(SEQ / BM, INTER / 48), 128, SMEM1>>>(
        (const __half*)px, (const __half*)pw1, b1, (__half*)ph);

    // GEMM2: out = h @ W2^T + b2   (fp32, 4096 x 2880)
    gemm2<<<dim3(SEQ / BM, HID / BN2), 128, SMEM2>>>(
        (const __half*)ph, (const __half*)pw2, b2, out);
}